// round 4
// baseline (speedup 1.0000x reference)
#include <cuda_runtime.h>
#include <cstdint>

// Problem constants
constexpr int S_LEN = 4096;
constexpr int DM    = 1024;
constexpr int NH    = 16;
constexpr int HD    = 64;
constexpr int QKV_N = 3 * DM;  // 3072

// Scratch device globals (allocation-free rule)
__device__ float g_x   [(size_t)S_LEN * DM];
__device__ float g_wqkv[(size_t)QKV_N * DM];
__device__ float g_wout[(size_t)DM * DM];
__device__ float g_qkv [(size_t)S_LEN * QKV_N];  // q pre-scaled by 0.125
__device__ float g_att [(size_t)S_LEN * DM];

// ---------------------------------------------------------------------------
// Helpers
// ---------------------------------------------------------------------------
__device__ __forceinline__ float tf32r(float x) {
    uint32_t u;
    asm("cvt.rna.tf32.f32 %0, %1;" : "=r"(u) : "f"(x));
    return __uint_as_float(u);
}

__device__ __forceinline__ void cp_async16(void* smem_dst, const void* gmem_src) {
    uint32_t s = (uint32_t)__cvta_generic_to_shared(smem_dst);
    asm volatile("cp.async.cg.shared.global [%0], [%1], 16;" :: "r"(s), "l"(gmem_src));
}
__device__ __forceinline__ void cp_commit() {
    asm volatile("cp.async.commit_group;");
}
template<int N>
__device__ __forceinline__ void cp_wait() {
    asm volatile("cp.async.wait_group %0;" :: "n"(N));
}

// m16n8k8 tf32 mma: D += A*B.
__device__ __forceinline__ void mma_tf32(float c[4], const float a[4],
                                         float b0, float b1) {
    asm volatile(
        "mma.sync.aligned.m16n8k8.row.col.f32.tf32.tf32.f32 "
        "{%0,%1,%2,%3}, {%4,%5,%6,%7}, {%8,%9}, {%0,%1,%2,%3};"
        : "+f"(c[0]), "+f"(c[1]), "+f"(c[2]), "+f"(c[3])
        : "r"(__float_as_uint(a[0])), "r"(__float_as_uint(a[1])),
          "r"(__float_as_uint(a[2])), "r"(__float_as_uint(a[3])),
          "r"(__float_as_uint(b0)),  "r"(__float_as_uint(b1)));
}

// ---------------------------------------------------------------------------
// Elementwise tf32 rounding pre-pass
// ---------------------------------------------------------------------------
__global__ void cvt_tf32_kernel(const float* __restrict__ in,
                                float* __restrict__ out, int n4) {
    int i = blockIdx.x * blockDim.x + threadIdx.x;
    if (i < n4) {
        float4 v = ((const float4*)in)[i];
        v.x = tf32r(v.x); v.y = tf32r(v.y);
        v.z = tf32r(v.z); v.w = tf32r(v.w);
        ((float4*)out)[i] = v;
    }
}

// ---------------------------------------------------------------------------
// TF32 GEMM: C[M,N] = A[M,K] * B[N,K]^T.  Block 128x128x32, 256 threads,
// 3-stage cp.async pipeline, ONE __syncthreads per K-iteration.
// MODE 1: round output to tf32, and pre-scale q columns (n0 < DM) by 0.125
//         (exact power-of-two; commutes with tf32 rounding).
// MODE 0: plain fp32 output.
// ---------------------------------------------------------------------------
constexpr int GSTG = 3;
constexpr int GEMM_SMEM = GSTG * 2 * 128 * 36 * (int)sizeof(float);  // 110592

template<int MODE>
__global__ __launch_bounds__(256, 2) void gemm_tf32(
    const float* __restrict__ A, const float* __restrict__ B,
    float* __restrict__ C, int M, int N, int K)
{
    extern __shared__ float sm[];
    float* AsBase = sm;                       // GSTG * 128*36
    float* BsBase = sm + GSTG * 128 * 36;     // GSTG * 128*36

    const int tid  = threadIdx.x;
    const int lane = tid & 31;
    const int wid  = tid >> 5;
    const int wm   = (wid >> 2) * 64;
    const int wn   = (wid & 3) * 32;
    const int m0   = blockIdx.y * 128;
    const int n0   = blockIdx.x * 128;

    const int ldr = tid >> 3;
    const int ldc = (tid & 7) * 4;

    const int NI = K / 32;

    auto issue_tile = [&](int it, int buf) {
        const float* Ag = A + (size_t)m0 * K + it * 32;
        const float* Bg = B + (size_t)n0 * K + it * 32;
        float* As = AsBase + buf * (128 * 36);
        float* Bs = BsBase + buf * (128 * 36);
#pragma unroll
        for (int p = 0; p < 4; ++p) {
            int row = p * 32 + ldr;
            cp_async16(&As[row * 36 + ldc], &Ag[(size_t)row * K + ldc]);
            cp_async16(&Bs[row * 36 + ldc], &Bg[(size_t)row * K + ldc]);
        }
        cp_commit();
    };

    float acc[4][4][4];
#pragma unroll
    for (int i = 0; i < 4; ++i)
#pragma unroll
        for (int j = 0; j < 4; ++j)
#pragma unroll
            for (int c = 0; c < 4; ++c) acc[i][j][c] = 0.f;

    issue_tile(0, 0);
    issue_tile(1, 1);

    for (int it = 0; it < NI; ++it) {
        if (it + 1 < NI) cp_wait<1>(); else cp_wait<0>();
        __syncthreads();                       // single barrier per iter
        if (it + 2 < NI) issue_tile(it + 2, (it + 2) % GSTG);

        const float* As = AsBase + (it % GSTG) * (128 * 36);
        const float* Bs = BsBase + (it % GSTG) * (128 * 36);

#pragma unroll
        for (int kk = 0; kk < 4; ++kk) {
            const int kb = kk * 8 + (lane & 3);
            float a[4][4];
#pragma unroll
            for (int mt = 0; mt < 4; ++mt) {
                int r = wm + mt * 16 + (lane >> 2);
                a[mt][0] = As[r * 36 + kb];
                a[mt][1] = As[(r + 8) * 36 + kb];
                a[mt][2] = As[r * 36 + kb + 4];
                a[mt][3] = As[(r + 8) * 36 + kb + 4];
            }
#pragma unroll
            for (int nt = 0; nt < 4; ++nt) {
                int cI = wn + nt * 8 + (lane >> 2);
                float b0 = Bs[cI * 36 + kb];
                float b1 = Bs[cI * 36 + kb + 4];
#pragma unroll
                for (int mt = 0; mt < 4; ++mt)
                    mma_tf32(acc[mt][nt], a[mt], b0, b1);
            }
        }
        // no trailing barrier: next iteration's top barrier protects reuse
    }

    // Epilogue. For MODE 1, q columns (n0 < DM) get exact 2^-3 pre-scale.
    const float oscale = (MODE == 1 && n0 < DM) ? 0.125f : 1.0f;
#pragma unroll
    for (int mt = 0; mt < 4; ++mt) {
#pragma unroll
        for (int nt = 0; nt < 4; ++nt) {
            int row = m0 + wm + mt * 16 + (lane >> 2);
            int col = n0 + wn + nt * 8 + 2 * (lane & 3);
            float v0 = acc[mt][nt][0] * oscale, v1 = acc[mt][nt][1] * oscale;
            float v2 = acc[mt][nt][2] * oscale, v3 = acc[mt][nt][3] * oscale;
            if (MODE == 1) { v0 = tf32r(v0); v1 = tf32r(v1); v2 = tf32r(v2); v3 = tf32r(v3); }
            *(float2*)&C[(size_t)row * N + col]       = make_float2(v0, v1);
            *(float2*)&C[(size_t)(row + 8) * N + col] = make_float2(v2, v3);
        }
    }
}

// ---------------------------------------------------------------------------
// Flash attention (tf32 mma, causal). Block = (128-row Q tile, head),
// 256 threads / 8 warps; warp w owns q rows [w*16, w*16+16) of the tile.
// KV tiles of 64 rows, 3-stage cp.async pipeline, ONE barrier per tile.
// Warps fully above the diagonal skip masked KV tiles.
// Smem: Qs[128][68], Ps[128][68], Ks[3][64][68], Vs[3][64][72] = 177152 B.
// ---------------------------------------------------------------------------
constexpr int FL_SMEM = (128 * 68 + 128 * 68 + 3 * 64 * 68 + 3 * 64 * 72) * (int)sizeof(float);

__global__ __launch_bounds__(256) void flash_tf32(
    const float* __restrict__ qkv, float* __restrict__ out)
{
    extern __shared__ float sm[];
    float* Qs  = sm;                         // 128*68
    float* Ps  = Qs + 128 * 68;              // 128*68
    float* KsB = Ps + 128 * 68;              // 3 * 64*68
    float* VsB = KsB + 3 * 64 * 68;          // 3 * 64*72

    const int tid  = threadIdx.x;
    const int lane = tid & 31;
    const int w    = tid >> 5;
    const int h    = blockIdx.y;
    const int qt   = (int)gridDim.x - 1 - (int)blockIdx.x;  // heavy first
    const int q0   = qt * 128;

    const float* qg = qkv + (size_t)q0 * QKV_N + h * HD;

    auto issue_kv = [&](int t, int buf) {
        const float* kg = qkv + (size_t)(t * 64) * QKV_N + DM + h * HD;
        const float* vg = kg + DM;
        float* Ks = KsB + buf * (64 * 68);
        float* Vs = VsB + buf * (64 * 72);
#pragma unroll
        for (int p = 0; p < 4; ++p) {
            int idx = tid + p * 256;          // 64 rows x 16 float4
            int row = idx >> 4;
            int c4  = (idx & 15) * 4;
            cp_async16(&Ks[row * 68 + c4], &kg[(size_t)row * QKV_N + c4]);
            cp_async16(&Vs[row * 72 + c4], &vg[(size_t)row * QKV_N + c4]);
        }
        cp_commit();
    };

    // Prologue: Q (group 0), KV tiles 0 and 1 (groups 1, 2)
    {
#pragma unroll
        for (int p = 0; p < 8; ++p) {
            int idx = tid + p * 256;          // 128 rows x 16 float4
            int row = idx >> 4;
            int c4  = (idx & 15) * 4;
            cp_async16(&Qs[row * 68 + c4], &qg[(size_t)row * QKV_N + c4]);
        }
        cp_commit();
    }
    const int tmax = 2 * qt + 1;              // KV tiles 0..tmax
    issue_kv(0, 0);
    if (tmax >= 1) issue_kv(1, 1);

    const int r  = (lane >> 2);
    const int qr = w * 16 + r;                // local q row (and qr+8)
    float m_i[2] = {-1e30f, -1e30f};
    float l_i[2] = {0.f, 0.f};
    float oacc[8][4];
#pragma unroll
    for (int n = 0; n < 8; ++n)
#pragma unroll
        for (int c = 0; c < 4; ++c) oacc[n][c] = 0.f;

    for (int t = 0; t <= tmax; ++t) {
        if (t < tmax) cp_wait<1>(); else cp_wait<0>();
        __syncthreads();                      // single barrier per KV tile
        if (t + 2 <= tmax) issue_kv(t + 2, (t + 2) % 3);

        // Warp-level causal skip: whole tile masked for this warp's rows?
        const int wrow_hi = q0 + w * 16 + 15; // max global row of this warp
        if (t * 64 > wrow_hi) continue;       // converges at top barrier

        const float* Ks = KsB + (t % 3) * (64 * 68);
        const float* Vs = VsB + (t % 3) * (64 * 72);

        // S = Q K^T  (Q pre-scaled by 0.125 upstream)
        float sacc[8][4];
#pragma unroll
        for (int n = 0; n < 8; ++n)
#pragma unroll
            for (int c = 0; c < 4; ++c) sacc[n][c] = 0.f;

#pragma unroll
        for (int kt = 0; kt < 8; ++kt) {
            const int kb = kt * 8 + (lane & 3);
            float a[4];
            a[0] = Qs[qr * 68 + kb];
            a[1] = Qs[(qr + 8) * 68 + kb];
            a[2] = Qs[qr * 68 + kb + 4];
            a[3] = Qs[(qr + 8) * 68 + kb + 4];
#pragma unroll
            for (int nt = 0; nt < 8; ++nt) {
                int cI = nt * 8 + (lane >> 2);
                float b0 = Ks[cI * 68 + kb];
                float b1 = Ks[cI * 68 + kb + 4];
                mma_tf32(sacc[nt], a, b0, b1);
            }
        }

        // Causal mask, only if this tile straddles this warp's diagonal
        if (t * 64 + 63 > q0 + w * 16) {
#pragma unroll
            for (int nt = 0; nt < 8; ++nt) {
#pragma unroll
                for (int c = 0; c < 4; ++c) {
                    int col_g = t * 64 + nt * 8 + 2 * (lane & 3) + (c & 1);
                    int row_g = q0 + qr + (c >> 1) * 8;
                    if (col_g > row_g) sacc[nt][c] = -1e30f;
                }
            }
        }

        // Online softmax
        float alpha[2];
#pragma unroll
        for (int half = 0; half < 2; ++half) {
            float mx = -1e30f;
#pragma unroll
            for (int nt = 0; nt < 8; ++nt) {
                mx = fmaxf(mx, sacc[nt][half * 2]);
                mx = fmaxf(mx, sacc[nt][half * 2 + 1]);
            }
            mx = fmaxf(mx, __shfl_xor_sync(0xffffffffu, mx, 1, 4));
            mx = fmaxf(mx, __shfl_xor_sync(0xffffffffu, mx, 2, 4));
            float mnew = fmaxf(m_i[half], mx);
            alpha[half] = __expf(m_i[half] - mnew);
            m_i[half] = mnew;
            float rs = 0.f;
#pragma unroll
            for (int nt = 0; nt < 8; ++nt) {
                float p0 = __expf(sacc[nt][half * 2]     - mnew);
                float p1 = __expf(sacc[nt][half * 2 + 1] - mnew);
                sacc[nt][half * 2]     = p0;
                sacc[nt][half * 2 + 1] = p1;
                rs += p0 + p1;
            }
            rs += __shfl_xor_sync(0xffffffffu, rs, 1, 4);
            rs += __shfl_xor_sync(0xffffffffu, rs, 2, 4);
            l_i[half] = l_i[half] * alpha[half] + rs;
        }

#pragma unroll
        for (int nt = 0; nt < 8; ++nt) {
            oacc[nt][0] *= alpha[0]; oacc[nt][1] *= alpha[0];
            oacc[nt][2] *= alpha[1]; oacc[nt][3] *= alpha[1];
        }

        // Stage P (tf32-rounded) into warp-private Ps rows
#pragma unroll
        for (int nt = 0; nt < 8; ++nt) {
            int col = nt * 8 + 2 * (lane & 3);
            Ps[qr * 68 + col]           = tf32r(sacc[nt][0]);
            Ps[qr * 68 + col + 1]       = tf32r(sacc[nt][1]);
            Ps[(qr + 8) * 68 + col]     = tf32r(sacc[nt][2]);
            Ps[(qr + 8) * 68 + col + 1] = tf32r(sacc[nt][3]);
        }
        __syncwarp();

        // O += P V
#pragma unroll
        for (int kt = 0; kt < 8; ++kt) {
            const int kb = kt * 8 + (lane & 3);
            float a[4];
            a[0] = Ps[qr * 68 + kb];
            a[1] = Ps[(qr + 8) * 68 + kb];
            a[2] = Ps[qr * 68 + kb + 4];
            a[3] = Ps[(qr + 8) * 68 + kb + 4];
#pragma unroll
            for (int nt = 0; nt < 8; ++nt) {
                int dI = nt * 8 + (lane >> 2);
                float b0 = Vs[kb * 72 + dI];
                float b1 = Vs[(kb + 4) * 72 + dI];
                mma_tf32(oacc[nt], a, b0, b1);
            }
        }
    }

    // Epilogue: normalize, round to tf32, store
    float inv0 = 1.f / l_i[0];
    float inv1 = 1.f / l_i[1];
#pragma unroll
    for (int nt = 0; nt < 8; ++nt) {
        int col = h * HD + nt * 8 + 2 * (lane & 3);
        int row = q0 + qr;
        *(float2*)&out[(size_t)row * DM + col] =
            make_float2(tf32r(oacc[nt][0] * inv0), tf32r(oacc[nt][1] * inv0));
        *(float2*)&out[(size_t)(row + 8) * DM + col] =
            make_float2(tf32r(oacc[nt][2] * inv1), tf32r(oacc[nt][3] * inv1));
    }
}

// ---------------------------------------------------------------------------
// Launch
// ---------------------------------------------------------------------------
extern "C" void kernel_launch(void* const* d_in, const int* in_sizes, int n_in,
                              void* d_out, int out_size)
{
    const float* x     = (const float*)d_in[0];
    const float* w_qkv = (const float*)d_in[1];
    const float* w_out = (const float*)d_in[2];
    float* out = (float*)d_out;

    float *xr, *wqkvr, *woutr, *qkvp, *attp;
    cudaGetSymbolAddress((void**)&xr,    g_x);
    cudaGetSymbolAddress((void**)&wqkvr, g_wqkv);
    cudaGetSymbolAddress((void**)&woutr, g_wout);
    cudaGetSymbolAddress((void**)&qkvp,  g_qkv);
    cudaGetSymbolAddress((void**)&attp,  g_att);

    cudaFuncSetAttribute(gemm_tf32<1>,
                         cudaFuncAttributeMaxDynamicSharedMemorySize, GEMM_SMEM);
    cudaFuncSetAttribute(gemm_tf32<0>,
                         cudaFuncAttributeMaxDynamicSharedMemorySize, GEMM_SMEM);
    cudaFuncSetAttribute(flash_tf32,
                         cudaFuncAttributeMaxDynamicSharedMemorySize, FL_SMEM);

    // 0) tf32-round the inputs
    {
        int n4;
        n4 = S_LEN * DM / 4;
        cvt_tf32_kernel<<<(n4 + 255) / 256, 256>>>(x, xr, n4);
        n4 = QKV_N * DM / 4;
        cvt_tf32_kernel<<<(n4 + 255) / 256, 256>>>(w_qkv, wqkvr, n4);
        n4 = DM * DM / 4;
        cvt_tf32_kernel<<<(n4 + 255) / 256, 256>>>(w_out, woutr, n4);
    }
    // 1) QKV projection (rounds output; pre-scales q by 0.125)
    {
        dim3 grid(QKV_N / 128, S_LEN / 128);
        gemm_tf32<1><<<grid, 256, GEMM_SMEM>>>(xr, wqkvr, qkvp, S_LEN, QKV_N, DM);
    }
    // 2) Flash attention
    {
        dim3 grid(S_LEN / 128, NH);
        flash_tf32<<<grid, 256, FL_SMEM>>>(qkvp, attp);
    }
    // 3) Output projection
    {
        dim3 grid(DM / 128, S_LEN / 128);
        gemm_tf32<0><<<grid, 256, GEMM_SMEM>>>(attp, woutr, out, S_LEN, DM, DM);
    }
}

// round 5
// speedup vs baseline: 1.1198x; 1.1198x over previous
#include <cuda_runtime.h>
#include <cstdint>

// Problem constants
constexpr int S_LEN = 4096;
constexpr int DM    = 1024;
constexpr int NH    = 16;
constexpr int HD    = 64;
constexpr int QKV_N = 3 * DM;  // 3072

// Scratch device globals (allocation-free rule)
__device__ float g_x   [(size_t)S_LEN * DM];
__device__ float g_wqkv[(size_t)QKV_N * DM];
__device__ float g_wout[(size_t)DM * DM];
__device__ float g_qkv [(size_t)S_LEN * QKV_N];  // q pre-scaled by 0.125
__device__ float g_att [(size_t)S_LEN * DM];

// ---------------------------------------------------------------------------
// Helpers
// ---------------------------------------------------------------------------
__device__ __forceinline__ float tf32r(float x) {
    uint32_t u;
    asm("cvt.rna.tf32.f32 %0, %1;" : "=r"(u) : "f"(x));
    return __uint_as_float(u);
}

__device__ __forceinline__ void cp_async16(void* smem_dst, const void* gmem_src) {
    uint32_t s = (uint32_t)__cvta_generic_to_shared(smem_dst);
    asm volatile("cp.async.cg.shared.global [%0], [%1], 16;" :: "r"(s), "l"(gmem_src));
}
__device__ __forceinline__ void cp_commit() {
    asm volatile("cp.async.commit_group;");
}
template<int N>
__device__ __forceinline__ void cp_wait() {
    asm volatile("cp.async.wait_group %0;" :: "n"(N));
}

// m16n8k8 tf32 mma: D += A*B.
__device__ __forceinline__ void mma_tf32(float c[4], const float a[4],
                                         float b0, float b1) {
    asm volatile(
        "mma.sync.aligned.m16n8k8.row.col.f32.tf32.tf32.f32 "
        "{%0,%1,%2,%3}, {%4,%5,%6,%7}, {%8,%9}, {%0,%1,%2,%3};"
        : "+f"(c[0]), "+f"(c[1]), "+f"(c[2]), "+f"(c[3])
        : "r"(__float_as_uint(a[0])), "r"(__float_as_uint(a[1])),
          "r"(__float_as_uint(a[2])), "r"(__float_as_uint(a[3])),
          "r"(__float_as_uint(b0)),  "r"(__float_as_uint(b1)));
}

// ---------------------------------------------------------------------------
// Elementwise tf32 rounding pre-pass
// ---------------------------------------------------------------------------
__global__ void cvt_tf32_kernel(const float* __restrict__ in,
                                float* __restrict__ out, int n4) {
    int i = blockIdx.x * blockDim.x + threadIdx.x;
    if (i < n4) {
        float4 v = ((const float4*)in)[i];
        v.x = tf32r(v.x); v.y = tf32r(v.y);
        v.z = tf32r(v.z); v.w = tf32r(v.w);
        ((float4*)out)[i] = v;
    }
}

// ---------------------------------------------------------------------------
// TF32 GEMM: C[M,N] = A[M,K] * B[N,K]^T.  Block 128x128x32, 256 threads,
// 3-stage cp.async pipeline, ONE __syncthreads per K-iteration.
// MODE 1: round output to tf32, pre-scale q columns (n0 < DM) by 0.125.
// MODE 0: plain fp32 output.
// ---------------------------------------------------------------------------
constexpr int GSTG = 3;
constexpr int GEMM_SMEM = GSTG * 2 * 128 * 36 * (int)sizeof(float);  // 110592

template<int MODE>
__global__ __launch_bounds__(256, 2) void gemm_tf32(
    const float* __restrict__ A, const float* __restrict__ B,
    float* __restrict__ C, int M, int N, int K)
{
    extern __shared__ float sm[];
    float* AsBase = sm;
    float* BsBase = sm + GSTG * 128 * 36;

    const int tid  = threadIdx.x;
    const int lane = tid & 31;
    const int wid  = tid >> 5;
    const int wm   = (wid >> 2) * 64;
    const int wn   = (wid & 3) * 32;
    const int m0   = blockIdx.y * 128;
    const int n0   = blockIdx.x * 128;

    const int ldr = tid >> 3;
    const int ldc = (tid & 7) * 4;

    const int NI = K / 32;

    auto issue_tile = [&](int it, int buf) {
        const float* Ag = A + (size_t)m0 * K + it * 32;
        const float* Bg = B + (size_t)n0 * K + it * 32;
        float* As = AsBase + buf * (128 * 36);
        float* Bs = BsBase + buf * (128 * 36);
#pragma unroll
        for (int p = 0; p < 4; ++p) {
            int row = p * 32 + ldr;
            cp_async16(&As[row * 36 + ldc], &Ag[(size_t)row * K + ldc]);
            cp_async16(&Bs[row * 36 + ldc], &Bg[(size_t)row * K + ldc]);
        }
        cp_commit();
    };

    float acc[4][4][4];
#pragma unroll
    for (int i = 0; i < 4; ++i)
#pragma unroll
        for (int j = 0; j < 4; ++j)
#pragma unroll
            for (int c = 0; c < 4; ++c) acc[i][j][c] = 0.f;

    issue_tile(0, 0);
    issue_tile(1, 1);

    for (int it = 0; it < NI; ++it) {
        if (it + 1 < NI) cp_wait<1>(); else cp_wait<0>();
        __syncthreads();                       // single barrier per iter
        if (it + 2 < NI) issue_tile(it + 2, (it + 2) % GSTG);

        const float* As = AsBase + (it % GSTG) * (128 * 36);
        const float* Bs = BsBase + (it % GSTG) * (128 * 36);

#pragma unroll
        for (int kk = 0; kk < 4; ++kk) {
            const int kb = kk * 8 + (lane & 3);
            float a[4][4];
#pragma unroll
            for (int mt = 0; mt < 4; ++mt) {
                int r = wm + mt * 16 + (lane >> 2);
                a[mt][0] = As[r * 36 + kb];
                a[mt][1] = As[(r + 8) * 36 + kb];
                a[mt][2] = As[r * 36 + kb + 4];
                a[mt][3] = As[(r + 8) * 36 + kb + 4];
            }
#pragma unroll
            for (int nt = 0; nt < 4; ++nt) {
                int cI = wn + nt * 8 + (lane >> 2);
                float b0 = Bs[cI * 36 + kb];
                float b1 = Bs[cI * 36 + kb + 4];
#pragma unroll
                for (int mt = 0; mt < 4; ++mt)
                    mma_tf32(acc[mt][nt], a[mt], b0, b1);
            }
        }
    }

    const float oscale = (MODE == 1 && n0 < DM) ? 0.125f : 1.0f;
#pragma unroll
    for (int mt = 0; mt < 4; ++mt) {
#pragma unroll
        for (int nt = 0; nt < 4; ++nt) {
            int row = m0 + wm + mt * 16 + (lane >> 2);
            int col = n0 + wn + nt * 8 + 2 * (lane & 3);
            float v0 = acc[mt][nt][0] * oscale, v1 = acc[mt][nt][1] * oscale;
            float v2 = acc[mt][nt][2] * oscale, v3 = acc[mt][nt][3] * oscale;
            if (MODE == 1) { v0 = tf32r(v0); v1 = tf32r(v1); v2 = tf32r(v2); v3 = tf32r(v3); }
            *(float2*)&C[(size_t)row * N + col]       = make_float2(v0, v1);
            *(float2*)&C[(size_t)(row + 8) * N + col] = make_float2(v2, v3);
        }
    }
}

// ---------------------------------------------------------------------------
// Flash attention (tf32 mma, causal). Block = (64-row Q tile, head).
// 128 threads / 4 warps; warp w owns q rows [w*16, w*16+16).
// 2-stage KV pipeline, ONE __syncthreads per KV tile.
// Smem: Qs[64][68], Ps[64][68], Ks[2][64][68], Vs[2][64][72] = 106496 B
// -> 2 blocks/SM (intra-block skew absorbed by co-resident block).
// ---------------------------------------------------------------------------
constexpr int FL_SMEM = (2 * 64 * 68 + 2 * 64 * 68 + 2 * 64 * 72) * (int)sizeof(float);

__global__ __launch_bounds__(128) void flash_tf32(
    const float* __restrict__ qkv, float* __restrict__ out)
{
    extern __shared__ float sm[];
    float* Qs  = sm;                       // 64*68
    float* Ps  = Qs + 64 * 68;             // 64*68
    float* KsB = Ps + 64 * 68;             // 2 * 64*68
    float* VsB = KsB + 2 * 64 * 68;        // 2 * 64*72

    const int tid  = threadIdx.x;
    const int lane = tid & 31;
    const int w    = tid >> 5;
    const int h    = blockIdx.y;
    const int qt   = (int)gridDim.x - 1 - (int)blockIdx.x;  // heavy first
    const int q0   = qt * 64;

    const int ldr = tid >> 4;              // 0..7
    const int ldc = (tid & 15) * 4;        // 0..60

    const float* qg = qkv + (size_t)q0 * QKV_N + h * HD;

    auto issue_kv = [&](int t, int buf) {
        const float* kg = qkv + (size_t)(t * 64) * QKV_N + DM + h * HD;
        const float* vg = kg + DM;
        float* Ks = KsB + buf * (64 * 68);
        float* Vs = VsB + buf * (64 * 72);
#pragma unroll
        for (int p = 0; p < 8; ++p) {
            int row = p * 8 + ldr;
            cp_async16(&Ks[row * 68 + ldc], &kg[(size_t)row * QKV_N + ldc]);
            cp_async16(&Vs[row * 72 + ldc], &vg[(size_t)row * QKV_N + ldc]);
        }
        cp_commit();
    };

    // Prologue: Q + KV tile 0
    {
#pragma unroll
        for (int p = 0; p < 8; ++p) {
            int row = p * 8 + ldr;
            cp_async16(&Qs[row * 68 + ldc], &qg[(size_t)row * QKV_N + ldc]);
        }
    }
    issue_kv(0, 0);

    const int r  = (lane >> 2);
    const int qr = w * 16 + r;             // local q row (and qr+8)
    float m_i[2] = {-1e30f, -1e30f};
    float l_i[2] = {0.f, 0.f};
    float oacc[8][4];
#pragma unroll
    for (int n = 0; n < 8; ++n)
#pragma unroll
        for (int c = 0; c < 4; ++c) oacc[n][c] = 0.f;

    for (int t = 0; t <= qt; ++t) {
        cp_wait<0>();                      // tile t (and Q on t=0) resident
        __syncthreads();                   // single barrier per KV tile
        if (t + 1 <= qt) issue_kv(t + 1, (t + 1) & 1);  // overlaps compute of t

        const float* Ks = KsB + (t & 1) * (64 * 68);
        const float* Vs = VsB + (t & 1) * (64 * 72);

        // S = Q K^T  (q pre-scaled by 0.125 upstream)
        float sacc[8][4];
#pragma unroll
        for (int n = 0; n < 8; ++n)
#pragma unroll
            for (int c = 0; c < 4; ++c) sacc[n][c] = 0.f;

#pragma unroll
        for (int kt = 0; kt < 8; ++kt) {
            const int kb = kt * 8 + (lane & 3);
            float a[4];
            a[0] = Qs[qr * 68 + kb];
            a[1] = Qs[(qr + 8) * 68 + kb];
            a[2] = Qs[qr * 68 + kb + 4];
            a[3] = Qs[(qr + 8) * 68 + kb + 4];
#pragma unroll
            for (int nt = 0; nt < 8; ++nt) {
                int cI = nt * 8 + (lane >> 2);
                float b0 = Ks[cI * 68 + kb];
                float b1 = Ks[cI * 68 + kb + 4];
                mma_tf32(sacc[nt], a, b0, b1);
            }
        }

        // Causal mask on the diagonal tile only
        if (t == qt) {
#pragma unroll
            for (int nt = 0; nt < 8; ++nt) {
#pragma unroll
                for (int c = 0; c < 4; ++c) {
                    int col = nt * 8 + 2 * (lane & 3) + (c & 1);
                    int rowL = qr + (c >> 1) * 8;
                    if (col > rowL) sacc[nt][c] = -1e30f;
                }
            }
        }

        // Online softmax: rows qr (c=0,1) and qr+8 (c=2,3)
        float alpha[2];
#pragma unroll
        for (int half = 0; half < 2; ++half) {
            float mx = -1e30f;
#pragma unroll
            for (int nt = 0; nt < 8; ++nt) {
                mx = fmaxf(mx, sacc[nt][half * 2]);
                mx = fmaxf(mx, sacc[nt][half * 2 + 1]);
            }
            mx = fmaxf(mx, __shfl_xor_sync(0xffffffffu, mx, 1, 4));
            mx = fmaxf(mx, __shfl_xor_sync(0xffffffffu, mx, 2, 4));
            float mnew = fmaxf(m_i[half], mx);
            alpha[half] = __expf(m_i[half] - mnew);
            m_i[half] = mnew;
            float rs = 0.f;
#pragma unroll
            for (int nt = 0; nt < 8; ++nt) {
                float p0 = __expf(sacc[nt][half * 2]     - mnew);
                float p1 = __expf(sacc[nt][half * 2 + 1] - mnew);
                sacc[nt][half * 2]     = p0;
                sacc[nt][half * 2 + 1] = p1;
                rs += p0 + p1;
            }
            rs += __shfl_xor_sync(0xffffffffu, rs, 1, 4);
            rs += __shfl_xor_sync(0xffffffffu, rs, 2, 4);
            l_i[half] = l_i[half] * alpha[half] + rs;
        }

#pragma unroll
        for (int nt = 0; nt < 8; ++nt) {
            oacc[nt][0] *= alpha[0]; oacc[nt][1] *= alpha[0];
            oacc[nt][2] *= alpha[1]; oacc[nt][3] *= alpha[1];
        }

        // Stage P (tf32-rounded) into warp-private Ps rows
#pragma unroll
        for (int nt = 0; nt < 8; ++nt) {
            int col = nt * 8 + 2 * (lane & 3);
            Ps[qr * 68 + col]           = tf32r(sacc[nt][0]);
            Ps[qr * 68 + col + 1]       = tf32r(sacc[nt][1]);
            Ps[(qr + 8) * 68 + col]     = tf32r(sacc[nt][2]);
            Ps[(qr + 8) * 68 + col + 1] = tf32r(sacc[nt][3]);
        }
        __syncwarp();

        // O += P V
#pragma unroll
        for (int kt = 0; kt < 8; ++kt) {
            const int kb = kt * 8 + (lane & 3);
            float a[4];
            a[0] = Ps[qr * 68 + kb];
            a[1] = Ps[(qr + 8) * 68 + kb];
            a[2] = Ps[qr * 68 + kb + 4];
            a[3] = Ps[(qr + 8) * 68 + kb + 4];
#pragma unroll
            for (int nt = 0; nt < 8; ++nt) {
                int dI = nt * 8 + (lane >> 2);
                float b0 = Vs[kb * 72 + dI];
                float b1 = Vs[(kb + 4) * 72 + dI];
                mma_tf32(oacc[nt], a, b0, b1);
            }
        }
        // no trailing barrier: next iteration's top barrier protects buffers
    }

    // Epilogue: normalize, round to tf32, store
    float inv0 = 1.f / l_i[0];
    float inv1 = 1.f / l_i[1];
#pragma unroll
    for (int nt = 0; nt < 8; ++nt) {
        int col = h * HD + nt * 8 + 2 * (lane & 3);
        int row = q0 + qr;
        *(float2*)&out[(size_t)row * DM + col] =
            make_float2(tf32r(oacc[nt][0] * inv0), tf32r(oacc[nt][1] * inv0));
        *(float2*)&out[(size_t)(row + 8) * DM + col] =
            make_float2(tf32r(oacc[nt][2] * inv1), tf32r(oacc[nt][3] * inv1));
    }
}

// ---------------------------------------------------------------------------
// Launch
// ---------------------------------------------------------------------------
extern "C" void kernel_launch(void* const* d_in, const int* in_sizes, int n_in,
                              void* d_out, int out_size)
{
    const float* x     = (const float*)d_in[0];
    const float* w_qkv = (const float*)d_in[1];
    const float* w_out = (const float*)d_in[2];
    float* out = (float*)d_out;

    float *xr, *wqkvr, *woutr, *qkvp, *attp;
    cudaGetSymbolAddress((void**)&xr,    g_x);
    cudaGetSymbolAddress((void**)&wqkvr, g_wqkv);
    cudaGetSymbolAddress((void**)&woutr, g_wout);
    cudaGetSymbolAddress((void**)&qkvp,  g_qkv);
    cudaGetSymbolAddress((void**)&attp,  g_att);

    cudaFuncSetAttribute(gemm_tf32<1>,
                         cudaFuncAttributeMaxDynamicSharedMemorySize, GEMM_SMEM);
    cudaFuncSetAttribute(gemm_tf32<0>,
                         cudaFuncAttributeMaxDynamicSharedMemorySize, GEMM_SMEM);
    cudaFuncSetAttribute(flash_tf32,
                         cudaFuncAttributeMaxDynamicSharedMemorySize, FL_SMEM);

    // 0) tf32-round the inputs
    {
        int n4;
        n4 = S_LEN * DM / 4;
        cvt_tf32_kernel<<<(n4 + 255) / 256, 256>>>(x, xr, n4);
        n4 = QKV_N * DM / 4;
        cvt_tf32_kernel<<<(n4 + 255) / 256, 256>>>(w_qkv, wqkvr, n4);
        n4 = DM * DM / 4;
        cvt_tf32_kernel<<<(n4 + 255) / 256, 256>>>(w_out, woutr, n4);
    }
    // 1) QKV projection (rounds output; pre-scales q by 0.125)
    {
        dim3 grid(QKV_N / 128, S_LEN / 128);
        gemm_tf32<1><<<grid, 256, GEMM_SMEM>>>(xr, wqkvr, qkvp, S_LEN, QKV_N, DM);
    }
    // 2) Flash attention
    {
        dim3 grid(S_LEN / 64, NH);
        flash_tf32<<<grid, 128, FL_SMEM>>>(qkvp, attp);
    }
    // 3) Output projection
    {
        dim3 grid(DM / 128, S_LEN / 128);
        gemm_tf32<0><<<grid, 256, GEMM_SMEM>>>(attp, woutr, out, S_LEN, DM, DM);
    }
}